// round 6
// baseline (speedup 1.0000x reference)
#include <cuda_runtime.h>
#include <cuda_bf16.h>
#include <math.h>
#include <stdint.h>

#define N_NODES 150000
#define N_ETYPES 1000
#define B_EDGES 16384
#define H 128
#define P_IN 336
#define P_HID 64

// Node GEMM: z[150000, 512] = A_ext[150000, 576] @ W_ext[576, 512]  (bf16-split)
// K passes: kt 0-11 A_hi x W_hi, kt 12-23 A_hi x W_lo, kt 24-35 A_lo x W_hi
// N layout: n = 4*h + g (gates interleaved)
#define KTILES 36
#define KSLICES 24             // stored W slices: 0-11 = W_hi, 12-23 = W_lo (hi dedup'd)
#define MTILE 128
#define M_TILES ((N_NODES + MTILE - 1) / MTILE)   // 1172
#define ASTRIDE 392            // padded K stride (bf16): conflict-free ldmatrix
#define A_BYTES (128 * ASTRIDE * 2)               // 100352
#define BSTAGE_OFF A_BYTES
#define NSTAGES 4
#define STAGE_BYTES 8192                           // 32 n8-blocks * 64 u32 * 4B
#define SMEM_BYTES (A_BYTES + NSTAGES * STAGE_BYTES)   // 133120

// W fragments (dedup'd): [slice(24)][n8(64)][lane(32)*2 u32]
__device__ __align__(16) uint32_t g_Wpack[KSLICES * 64 * 64];

// ---------------------------------------------------------------------------
__device__ __forceinline__ unsigned short f2bf_bits(float f) {
    return __bfloat16_as_ushort(__float2bfloat16_rn(f));
}
__device__ __forceinline__ float bf_val(unsigned short u) {
    return __bfloat162float(__ushort_as_bfloat16(u));
}
__device__ __forceinline__ float sigmoidf_(float x) { return 1.0f / (1.0f + expf(-x)); }

__device__ __forceinline__ uint32_t smem_u32(const void* p) {
    uint32_t a;
    asm("{ .reg .u64 t; cvta.to.shared.u64 t, %1; cvt.u32.u64 %0, t; }"
        : "=r"(a) : "l"(p));
    return a;
}
__device__ __forceinline__ void ldmatrix_x4(uint32_t* r, uint32_t addr) {
    asm volatile("ldmatrix.sync.aligned.m8n8.x4.shared.b16 {%0,%1,%2,%3}, [%4];"
        : "=r"(r[0]), "=r"(r[1]), "=r"(r[2]), "=r"(r[3]) : "r"(addr));
}
__device__ __forceinline__ void mma16816(float* c, const uint32_t* a, uint2 b) {
    asm volatile("mma.sync.aligned.m16n8k16.row.col.f32.bf16.bf16.f32 "
        "{%0,%1,%2,%3}, {%4,%5,%6,%7}, {%8,%9}, {%0,%1,%2,%3};"
        : "+f"(c[0]), "+f"(c[1]), "+f"(c[2]), "+f"(c[3])
        : "r"(a[0]), "r"(a[1]), "r"(a[2]), "r"(a[3]), "r"(b.x), "r"(b.y));
}
__device__ __forceinline__ void cp_async16(uint32_t dst, const void* src) {
    asm volatile("cp.async.cg.shared.global [%0], [%1], 16;"
                 :: "r"(dst), "l"(src) : "memory");
}

// ---------------------------------------------------------------------------
// W_ext element (bf16 bits): kk in [0,192) = hi of k, [192,384) = lo of k.
// ---------------------------------------------------------------------------
__device__ __forceinline__ unsigned short wext_bits(
    int kk, int n, const float* Wx, const float* Wh, const float* bg)
{
    int k; bool want_lo = false;
    if (kk < 192) k = kk;
    else          { k = kk - 192; want_lo = true; }
    int g = n & 3, h = n >> 2;
    float w;
    if (k < 128)       w = Wh[(g * 128 + k) * 128 + h];
    else if (k < 178)  w = Wx[(g * 50 + (k - 128)) * 128 + h];
    else if (k == 178) w = bg[g * 128 + h];
    else               w = 0.0f;
    unsigned short hi = f2bf_bits(w);
    if (!want_lo) return hi;
    return f2bf_bits(w - bf_val(hi));
}

__global__ void prep_weights_kernel(const float* __restrict__ Wx,
                                    const float* __restrict__ Wh,
                                    const float* __restrict__ bg)
{
    int idx = blockIdx.x * blockDim.x + threadIdx.x;
    if (idx >= KSLICES * 64 * 64) return;
    int r    = idx & 63;
    int lane = r >> 1, reg = r & 1;
    int blk  = idx >> 6;
    int sl   = blk >> 6, n8 = blk & 63;
    int n    = n8 * 8 + (lane >> 2);
    int kk0  = ((sl < 12) ? sl * 16 : 192 + (sl - 12) * 16)
               + (lane & 3) * 2 + reg * 8;
    unsigned short u0 = wext_bits(kk0,     n, Wx, Wh, bg);
    unsigned short u1 = wext_bits(kk0 + 1, n, Wx, Wh, bg);
    g_Wpack[idx] = (uint32_t)u0 | ((uint32_t)u1 << 16);
}

// ---------------------------------------------------------------------------
// Node update: bf16-split mma.sync GEMM + fused peephole LSTM.
// 512 threads = 16 warps (4m x 4n), CTA tile 128 nodes x 256 cols (= 64 h).
// B streamed via 4-stage cp.async ring (distance 3).
// ---------------------------------------------------------------------------
__global__ void __launch_bounds__(512, 1) node_update_mma_kernel(
    const float* __restrict__ node_cont,
    const int*   __restrict__ ncat_codes,
    const float* __restrict__ ncat_emb,
    const float* __restrict__ h_prev,
    const float* __restrict__ c_prev,
    const float* __restrict__ w_c,
    float* __restrict__ h_new,
    float* __restrict__ c_new)
{
    extern __shared__ __align__(16) unsigned char smraw[];
    __nv_bfloat16* As  = (__nv_bfloat16*)smraw;   // [128][ASTRIDE]
    float*         zsm = (float*)smraw;           // reused post-GEMM: [64][256]

    const int tid  = threadIdx.x;
    const int lane = tid & 31;
    const int wid  = tid >> 5;
    const int wm   = wid & 3;
    const int wn   = wid >> 2;
    const int mtile = blockIdx.x >> 1;
    const int chunk = blockIdx.x & 1;
    const int n0m   = mtile * MTILE;

    // per-chunk B source: 32 n8-blocks (2048 u32 = 8KB) per slice
    const uint32_t* gsrc_base = g_Wpack + (size_t)chunk * 32 * 64;
    const uint32_t  bstage0   = smem_u32(smraw + BSTAGE_OFF);

    // ---- prologue: launch B stages 0..2 under the A-build
    #pragma unroll
    for (int p = 0; p < 3; ++p) {
        cp_async16(bstage0 + p * STAGE_BYTES + tid * 16,
                   gsrc_base + p * 4096 + tid * 4);
        asm volatile("cp.async.commit_group;" ::: "memory");
    }

    // ---- A build: hi cols [0,192), lo cols [192,384)
    #pragma unroll
    for (int it = 0; it < 4; ++it) {
        int cid = tid + it * 512;
        int row = cid >> 4, kb = (cid & 15) << 3;
        int node = n0m + row;
        float f[8];
        if (node < N_NODES) {
            const float4* hp = (const float4*)(h_prev + (size_t)node * H + kb);
            float4 a = hp[0], b = hp[1];
            f[0]=a.x; f[1]=a.y; f[2]=a.z; f[3]=a.w;
            f[4]=b.x; f[5]=b.y; f[6]=b.z; f[7]=b.w;
        } else {
            #pragma unroll
            for (int q = 0; q < 8; ++q) f[q] = 0.0f;
        }
        uint32_t hw[4], lw[4];
        #pragma unroll
        for (int q = 0; q < 4; ++q) {
            unsigned short h0 = f2bf_bits(f[2*q]),   h1 = f2bf_bits(f[2*q+1]);
            unsigned short l0 = f2bf_bits(f[2*q]   - bf_val(h0));
            unsigned short l1 = f2bf_bits(f[2*q+1] - bf_val(h1));
            hw[q] = (uint32_t)h0 | ((uint32_t)h1 << 16);
            lw[q] = (uint32_t)l0 | ((uint32_t)l1 << 16);
        }
        *(uint4*)&As[row * ASTRIDE + kb]       = make_uint4(hw[0], hw[1], hw[2], hw[3]);
        *(uint4*)&As[row * ASTRIDE + 192 + kb] = make_uint4(lw[0], lw[1], lw[2], lw[3]);
    }
    #pragma unroll 2
    for (int it = 0; it < 16; ++it) {
        int e = tid + it * 512;
        int row = e >> 6, kr = e & 63;
        int node = n0m + row;
        float v = 0.0f;
        if (node < N_NODES) {
            if (kr < 2)        v = node_cont[node * 2 + kr];
            else if (kr < 50)  {
                int j = (kr - 2) >> 4, kd = (kr - 2) & 15;
                int code = ncat_codes[j * N_NODES + node];
                v = ncat_emb[(j * 64 + code) * 16 + kd];
            } else if (kr == 50) v = 1.0f;
        }
        unsigned short hi = f2bf_bits(v);
        As[row * ASTRIDE + 128 + kr] = __ushort_as_bfloat16(hi);
        As[row * ASTRIDE + 320 + kr] = __ushort_as_bfloat16(f2bf_bits(v - bf_val(hi)));
    }

    // ---- GEMM mainloop
    float acc[2][8][4];
    #pragma unroll
    for (int mt = 0; mt < 2; ++mt)
        #pragma unroll
        for (int nt = 0; nt < 8; ++nt)
            #pragma unroll
            for (int q = 0; q < 4; ++q) acc[mt][nt][q] = 0.0f;

    const uint32_t as_base = smem_u32(As);
    const uint32_t blane   = (uint32_t)(wn * 8 * 64 + lane * 2) * 4;

    #pragma unroll 4
    for (int kt = 0; kt < KTILES; ++kt) {
        asm volatile("cp.async.wait_group 2;" ::: "memory");
        __syncthreads();   // stage kt visible to all (also covers A-build at kt=0)

        // issue stage kt+3 (overwrites stage consumed at kt-1)
        if (kt + 3 < KTILES) {
            int sn = kt + 3;
            int sl = (sn < KSLICES) ? sn : sn - KSLICES;
            cp_async16(bstage0 + ((kt + 3) & 3) * STAGE_BYTES + tid * 16,
                       gsrc_base + sl * 4096 + tid * 4);
        }
        asm volatile("cp.async.commit_group;" ::: "memory");

        int acol = (kt < 12) ? kt * 16
                 : (kt < 24) ? (kt - 12) * 16
                 : 192 + (kt - 24) * 16;
        uint32_t a[2][4];
        #pragma unroll
        for (int mt = 0; mt < 2; ++mt) {
            uint32_t addr = as_base +
                ((uint32_t)(wm * 32 + mt * 16 + (lane & 15)) * ASTRIDE
                 + acol + (lane >> 4) * 8) * 2;
            ldmatrix_x4(a[mt], addr);
        }
        uint2 b[8];
        uint32_t bs = bstage0 + (kt & 3) * STAGE_BYTES + blane;
        #pragma unroll
        for (int nt = 0; nt < 8; ++nt)
            asm volatile("ld.shared.v2.u32 {%0,%1}, [%2];"
                         : "=r"(b[nt].x), "=r"(b[nt].y) : "r"(bs + nt * 256));
        #pragma unroll
        for (int nt = 0; nt < 8; ++nt) {
            mma16816(acc[0][nt], a[0], b[nt]);
            mma16816(acc[1][nt], a[1], b[nt]);
        }
    }

    // ---- epilogue: two 64-node halves through smem, fused LSTM
    const int group = lane >> 2;
    const int qq    = lane & 3;
    #pragma unroll
    for (int half = 0; half < 2; ++half) {
        __syncthreads();
        if ((wm >> 1) == half) {
            int rbase = (wm & 1) * 32;
            #pragma unroll
            for (int mt = 0; mt < 2; ++mt) {
                int r = rbase + mt * 16 + group;
                #pragma unroll
                for (int nt = 0; nt < 8; ++nt) {
                    int l = wn * 64 + nt * 8 + qq * 2;
                    *(float2*)&zsm[r * 256 + l] =
                        make_float2(acc[mt][nt][0], acc[mt][nt][1]);
                    *(float2*)&zsm[(r + 8) * 256 + l] =
                        make_float2(acc[mt][nt][2], acc[mt][nt][3]);
                }
            }
        }
        __syncthreads();
        #pragma unroll
        for (int i = 0; i < 8; ++i) {
            int cell = tid + i * 512;
            int nl = cell >> 6, hl = cell & 63;
            int node = n0m + half * 64 + nl;
            if (node < N_NODES) {
                int h = chunk * 64 + hl;
                float4 z = *(const float4*)&zsm[nl * 256 + hl * 4];
                size_t off = (size_t)node * H + h;
                float cv = c_prev[off];
                float ig = sigmoidf_(z.x + w_c[h] * cv);
                float fg = sigmoidf_(z.y + w_c[128 + h] * cv);
                float tg = tanhf(z.z);
                float cn = fg * cv + ig * tg;
                float og = sigmoidf_(z.w + w_c[256 + h] * cn);
                c_new[off] = cn;
                h_new[off] = og * tanhf(cn);
            }
        }
    }
}

// ---------------------------------------------------------------------------
// Edge MLP: 16 edges per block (256 thr = 4 groups x 64 j, 4 edges/thread).
// ---------------------------------------------------------------------------
__global__ void __launch_bounds__(256) edge_mlp_kernel(
    const int*   __restrict__ src_ids, const int* __restrict__ dst_ids,
    const int*   __restrict__ etype_ids, const float* __restrict__ t_rel,
    const int*   __restrict__ ecat_codes, const float* __restrict__ eid_emb,
    const float* __restrict__ ecat_emb, const float* __restrict__ time_W,
    const float* __restrict__ time_b,
    const float* __restrict__ W1,
    const float* __restrict__ b1, const float* __restrict__ W2,
    const float* __restrict__ b2, const float* __restrict__ h_new,
    float* __restrict__ prob)
{
    __shared__ float comb[16][P_IN];
    __shared__ float part[4][2][4];

    const int tid  = threadIdx.x;
    const int g    = tid >> 6;
    const int j    = tid & 63;
    const int base = blockIdx.x * 16;

    for (int idx = tid; idx < 16 * P_IN; idx += 256) {
        int le  = idx / P_IN;
        int off = idx - le * P_IN;
        int b = base + le;
        float v;
        if (off < 128) {
            v = h_new[(size_t)src_ids[b] * H + off];
        } else if (off < 256) {
            v = h_new[(size_t)dst_ids[b] * H + (off - 128)];
        } else {
            int e = etype_ids[b];
            if (off < 288)       v = eid_emb[e * 32 + (off - 256)];
            else if (off < 304)  { int c0 = ecat_codes[e];
                                   v = ecat_emb[c0 * 16 + (off - 288)]; }
            else if (off < 320)  { int c1 = ecat_codes[N_ETYPES + e];
                                   v = ecat_emb[(32 + c1) * 16 + (off - 304)]; }
            else                 { int k = off - 320;
                                   v = fmaf(t_rel[b], time_W[k], time_b[k]); }
        }
        comb[le][off] = v;
    }
    __syncthreads();

    float bj = b1[j];
    float h0 = bj, h1 = bj, h2 = bj, h3 = bj;
    const float* c0 = comb[g * 4 + 0];
    const float* c1 = comb[g * 4 + 1];
    const float* c2 = comb[g * 4 + 2];
    const float* c3 = comb[g * 4 + 3];
    #pragma unroll 4
    for (int i = 0; i < P_IN; ++i) {
        float w = W1[i * P_HID + j];
        h0 = fmaf(c0[i], w, h0);
        h1 = fmaf(c1[i], w, h1);
        h2 = fmaf(c2[i], w, h2);
        h3 = fmaf(c3[i], w, h3);
    }
    float w2 = W2[j];
    float v0 = fmaxf(h0, 0.0f) * w2;
    float v1 = fmaxf(h1, 0.0f) * w2;
    float v2 = fmaxf(h2, 0.0f) * w2;
    float v3 = fmaxf(h3, 0.0f) * w2;

    #pragma unroll
    for (int off = 16; off > 0; off >>= 1) {
        v0 += __shfl_down_sync(0xffffffffu, v0, off);
        v1 += __shfl_down_sync(0xffffffffu, v1, off);
        v2 += __shfl_down_sync(0xffffffffu, v2, off);
        v3 += __shfl_down_sync(0xffffffffu, v3, off);
    }
    if ((j & 31) == 0) {
        int wh = j >> 5;
        part[g][wh][0] = v0; part[g][wh][1] = v1;
        part[g][wh][2] = v2; part[g][wh][3] = v3;
    }
    __syncthreads();
    if (j < 4) {
        float zsum = part[g][0][j] + part[g][1][j] + b2[0];
        prob[base + g * 4 + j] = 1.0f / (1.0f + expf(-zsum));
    }
}

// ---------------------------------------------------------------------------
extern "C" void kernel_launch(void* const* d_in, const int* in_sizes, int n_in,
                              void* d_out, int out_size)
{
    const int*   src_ids    = (const int*)  d_in[0];
    const int*   dst_ids    = (const int*)  d_in[1];
    const int*   etype_ids  = (const int*)  d_in[2];
    const float* t_rel      = (const float*)d_in[3];
    const float* node_cont  = (const float*)d_in[4];
    const int*   ncat_codes = (const int*)  d_in[5];
    const int*   ecat_codes = (const int*)  d_in[6];
    /* d_in[7] = edge_index, unused */
    const float* h_prev     = (const float*)d_in[8];
    const float* c_prev     = (const float*)d_in[9];
    const float* ncat_emb   = (const float*)d_in[10];
    const float* eid_emb    = (const float*)d_in[11];
    const float* ecat_emb   = (const float*)d_in[12];
    const float* time_W     = (const float*)d_in[13];
    const float* time_b     = (const float*)d_in[14];
    const float* Wx         = (const float*)d_in[15];
    const float* Wh         = (const float*)d_in[16];
    const float* b_gate     = (const float*)d_in[17];
    const float* w_c        = (const float*)d_in[18];
    const float* W1         = (const float*)d_in[19];
    const float* b1         = (const float*)d_in[20];
    const float* W2         = (const float*)d_in[21];
    const float* b2         = (const float*)d_in[22];

    float* out   = (float*)d_out;
    float* prob  = out;
    float* h_new = out + B_EDGES;
    float* c_new = out + B_EDGES + (size_t)N_NODES * H;

    cudaFuncSetAttribute(node_update_mma_kernel,
                         cudaFuncAttributeMaxDynamicSharedMemorySize, SMEM_BYTES);

    prep_weights_kernel<<<(KSLICES * 64 * 64 + 255) / 256, 256>>>(Wx, Wh, b_gate);

    node_update_mma_kernel<<<M_TILES * 2, 512, SMEM_BYTES>>>(
        node_cont, ncat_codes, ncat_emb, h_prev, c_prev, w_c, h_new, c_new);

    edge_mlp_kernel<<<B_EDGES / 16, 256>>>(
        src_ids, dst_ids, etype_ids, t_rel,
        ecat_codes, eid_emb, ecat_emb, time_W, time_b,
        W1, b1, W2, b2, h_new, prob);
}

// round 7
// speedup vs baseline: 1.1293x; 1.1293x over previous
#include <cuda_runtime.h>
#include <cuda_fp16.h>
#include <math.h>
#include <stdint.h>

#define N_NODES 150000
#define N_ETYPES 1000
#define B_EDGES 16384
#define H 128
#define P_IN 336
#define P_HID 64

// Node GEMM: z[150000, 512] = A_ext[150000, 384] @ W_ext[384, 512]  (fp16 2-pass)
// A_ext = [A_hi | A_lo]  (fp16 split of A: exact to 2^-22)
// W_ext = [W_h16 ; W_h16] (same fp16 weights for both K blocks)
// => z = (A_hi + A_lo) . W_h16 = A . fl16(W); only W quantization error (~2.8e-4 rms)
// N layout: n = 4*h + g (gates interleaved)
#define KTILES 24
#define KSLICES 12             // stored W slices (kt 12-23 reuse slices 0-11)
#define MTILE 128
#define M_TILES ((N_NODES + MTILE - 1) / MTILE)   // 1172
#define ASTRIDE 392            // padded K stride (fp16): conflict-free ldmatrix
#define SMEM_BYTES (128 * ASTRIDE * 2)            // 100352

// W fragments: [slice(12)][n8(64)][lane(32)*2 u32]
__device__ __align__(16) uint32_t g_Wpack[KSLICES * 64 * 64];

// ---------------------------------------------------------------------------
__device__ __forceinline__ unsigned short f2h_bits(float f) {
    return __half_as_ushort(__float2half_rn(f));
}
__device__ __forceinline__ float h_val(unsigned short u) {
    return __half2float(__ushort_as_half(u));
}
__device__ __forceinline__ float sigmoidf_(float x) { return 1.0f / (1.0f + expf(-x)); }

__device__ __forceinline__ uint32_t smem_u32(const void* p) {
    uint32_t a;
    asm("{ .reg .u64 t; cvta.to.shared.u64 t, %1; cvt.u32.u64 %0, t; }"
        : "=r"(a) : "l"(p));
    return a;
}
__device__ __forceinline__ void ldmatrix_x4(uint32_t* r, uint32_t addr) {
    asm volatile("ldmatrix.sync.aligned.m8n8.x4.shared.b16 {%0,%1,%2,%3}, [%4];"
        : "=r"(r[0]), "=r"(r[1]), "=r"(r[2]), "=r"(r[3]) : "r"(addr));
}
__device__ __forceinline__ void mma16816(float* c, const uint32_t* a, uint2 b) {
    asm volatile("mma.sync.aligned.m16n8k16.row.col.f32.f16.f16.f32 "
        "{%0,%1,%2,%3}, {%4,%5,%6,%7}, {%8,%9}, {%0,%1,%2,%3};"
        : "+f"(c[0]), "+f"(c[1]), "+f"(c[2]), "+f"(c[3])
        : "r"(a[0]), "r"(a[1]), "r"(a[2]), "r"(a[3]), "r"(b.x), "r"(b.y));
}

// ---------------------------------------------------------------------------
// W element (fp16 bits) at K index k in [0,192), output col n.
// ---------------------------------------------------------------------------
__device__ __forceinline__ unsigned short w_bits(
    int k, int n, const float* Wx, const float* Wh, const float* bg)
{
    int g = n & 3, h = n >> 2;
    float w;
    if (k < 128)       w = Wh[(g * 128 + k) * 128 + h];
    else if (k < 178)  w = Wx[(g * 50 + (k - 128)) * 128 + h];
    else if (k == 178) w = bg[g * 128 + h];
    else               w = 0.0f;
    return f2h_bits(w);
}

__global__ void prep_weights_kernel(const float* __restrict__ Wx,
                                    const float* __restrict__ Wh,
                                    const float* __restrict__ bg)
{
    int idx = blockIdx.x * blockDim.x + threadIdx.x;
    if (idx >= KSLICES * 64 * 64) return;
    int r    = idx & 63;          // lane*2 + reg
    int lane = r >> 1, reg = r & 1;
    int blk  = idx >> 6;          // sl*64 + n8
    int sl   = blk >> 6, n8 = blk & 63;
    int n    = n8 * 8 + (lane >> 2);
    int k0   = sl * 16 + (lane & 3) * 2 + reg * 8;
    unsigned short u0 = w_bits(k0,     n, Wx, Wh, bg);
    unsigned short u1 = w_bits(k0 + 1, n, Wx, Wh, bg);
    g_Wpack[idx] = (uint32_t)u0 | ((uint32_t)u1 << 16);
}

// ---------------------------------------------------------------------------
// Node update: fp16 2-pass mma.sync GEMM + fused peephole LSTM.
// 512 threads = 16 warps (4m x 4n), CTA tile 128 nodes x 256 cols (= 64 h).
// (Verified R5 mainloop structure, 24 kt instead of 36.)
// ---------------------------------------------------------------------------
__global__ void __launch_bounds__(512, 1) node_update_mma_kernel(
    const float* __restrict__ node_cont,
    const int*   __restrict__ ncat_codes,
    const float* __restrict__ ncat_emb,
    const float* __restrict__ h_prev,
    const float* __restrict__ c_prev,
    const float* __restrict__ w_c,
    float* __restrict__ h_new,
    float* __restrict__ c_new)
{
    extern __shared__ __align__(16) unsigned char smraw[];
    unsigned short* As  = (unsigned short*)smraw;  // [128][ASTRIDE] fp16 bits
    float*          zsm = (float*)smraw;           // reused post-GEMM: [64][256]

    const int tid  = threadIdx.x;
    const int lane = tid & 31;
    const int wid  = tid >> 5;
    const int wm   = wid & 3;
    const int wn   = wid >> 2;
    const int mtile = blockIdx.x >> 1;
    const int chunk = blockIdx.x & 1;
    const int n0m   = mtile * MTILE;

    // ---- A build: hi cols [0,192), lo cols [192,384)
    #pragma unroll
    for (int it = 0; it < 4; ++it) {
        int cid = tid + it * 512;
        int row = cid >> 4, kb = (cid & 15) << 3;
        int node = n0m + row;
        float f[8];
        if (node < N_NODES) {
            const float4* hp = (const float4*)(h_prev + (size_t)node * H + kb);
            float4 a = hp[0], b = hp[1];
            f[0]=a.x; f[1]=a.y; f[2]=a.z; f[3]=a.w;
            f[4]=b.x; f[5]=b.y; f[6]=b.z; f[7]=b.w;
        } else {
            #pragma unroll
            for (int q = 0; q < 8; ++q) f[q] = 0.0f;
        }
        uint32_t hw[4], lw[4];
        #pragma unroll
        for (int q = 0; q < 4; ++q) {
            unsigned short h0 = f2h_bits(f[2*q]),   h1 = f2h_bits(f[2*q+1]);
            unsigned short l0 = f2h_bits(f[2*q]   - h_val(h0));
            unsigned short l1 = f2h_bits(f[2*q+1] - h_val(h1));
            hw[q] = (uint32_t)h0 | ((uint32_t)h1 << 16);
            lw[q] = (uint32_t)l0 | ((uint32_t)l1 << 16);
        }
        *(uint4*)&As[row * ASTRIDE + kb]       = make_uint4(hw[0], hw[1], hw[2], hw[3]);
        *(uint4*)&As[row * ASTRIDE + 192 + kb] = make_uint4(lw[0], lw[1], lw[2], lw[3]);
    }
    #pragma unroll 2
    for (int it = 0; it < 16; ++it) {
        int e = tid + it * 512;
        int row = e >> 6, kr = e & 63;
        int node = n0m + row;
        float v = 0.0f;
        if (node < N_NODES) {
            if (kr < 2)        v = node_cont[node * 2 + kr];
            else if (kr < 50)  {
                int j = (kr - 2) >> 4, kd = (kr - 2) & 15;
                int code = ncat_codes[j * N_NODES + node];
                v = ncat_emb[(j * 64 + code) * 16 + kd];
            } else if (kr == 50) v = 1.0f;
        }
        unsigned short hi = f2h_bits(v);
        As[row * ASTRIDE + 128 + kr] = hi;
        As[row * ASTRIDE + 320 + kr] = f2h_bits(v - h_val(hi));
    }
    __syncthreads();

    // ---- GEMM mainloop (R5-verified structure, 24 kt)
    float acc[2][8][4];
    #pragma unroll
    for (int mt = 0; mt < 2; ++mt)
        #pragma unroll
        for (int nt = 0; nt < 8; ++nt)
            #pragma unroll
            for (int q = 0; q < 4; ++q) acc[mt][nt][q] = 0.0f;

    const uint32_t as_base = smem_u32(As);
    const uint32_t* __restrict__ wp_base =
        g_Wpack + (size_t)(chunk * 32 + wn * 8) * 64 + lane * 2;

    #pragma unroll 2
    for (int kt = 0; kt < KTILES; ++kt) {
        int acol = (kt < 12) ? kt * 16 : 192 + (kt - 12) * 16;
        int sl   = (kt < KSLICES) ? kt : kt - KSLICES;   // both passes share W
        uint32_t a[2][4];
        #pragma unroll
        for (int mt = 0; mt < 2; ++mt) {
            uint32_t addr = as_base +
                ((uint32_t)(wm * 32 + mt * 16 + (lane & 15)) * ASTRIDE
                 + acol + (lane >> 4) * 8) * 2;
            ldmatrix_x4(a[mt], addr);
        }
        uint2 b[8];
        const uint32_t* wp = wp_base + sl * 4096;   // 64 n8 * 64 u32
        #pragma unroll
        for (int nt = 0; nt < 8; ++nt) b[nt] = *(const uint2*)(wp + nt * 64);
        #pragma unroll
        for (int nt = 0; nt < 8; ++nt) {
            mma16816(acc[0][nt], a[0], b[nt]);
            mma16816(acc[1][nt], a[1], b[nt]);
        }
    }

    // ---- epilogue: two 64-node halves through smem, fused LSTM
    const int group = lane >> 2;
    const int qq    = lane & 3;
    #pragma unroll
    for (int half = 0; half < 2; ++half) {
        __syncthreads();
        if ((wm >> 1) == half) {
            int rbase = (wm & 1) * 32;
            #pragma unroll
            for (int mt = 0; mt < 2; ++mt) {
                int r = rbase + mt * 16 + group;
                #pragma unroll
                for (int nt = 0; nt < 8; ++nt) {
                    int l = wn * 64 + nt * 8 + qq * 2;
                    *(float2*)&zsm[r * 256 + l] =
                        make_float2(acc[mt][nt][0], acc[mt][nt][1]);
                    *(float2*)&zsm[(r + 8) * 256 + l] =
                        make_float2(acc[mt][nt][2], acc[mt][nt][3]);
                }
            }
        }
        __syncthreads();
        #pragma unroll
        for (int i = 0; i < 8; ++i) {
            int cell = tid + i * 512;
            int nl = cell >> 6, hl = cell & 63;
            int node = n0m + half * 64 + nl;
            if (node < N_NODES) {
                int h = chunk * 64 + hl;
                float4 z = *(const float4*)&zsm[nl * 256 + hl * 4];
                size_t off = (size_t)node * H + h;
                float cv = c_prev[off];
                float ig = sigmoidf_(z.x + w_c[h] * cv);
                float fg = sigmoidf_(z.y + w_c[128 + h] * cv);
                float tg = tanhf(z.z);
                float cn = fg * cv + ig * tg;
                float og = sigmoidf_(z.w + w_c[256 + h] * cn);
                c_new[off] = cn;
                h_new[off] = og * tanhf(cn);
            }
        }
    }
}

// ---------------------------------------------------------------------------
// Edge MLP: 16 edges per block (256 thr = 4 groups x 64 j, 4 edges/thread).
// ---------------------------------------------------------------------------
__global__ void __launch_bounds__(256) edge_mlp_kernel(
    const int*   __restrict__ src_ids, const int* __restrict__ dst_ids,
    const int*   __restrict__ etype_ids, const float* __restrict__ t_rel,
    const int*   __restrict__ ecat_codes, const float* __restrict__ eid_emb,
    const float* __restrict__ ecat_emb, const float* __restrict__ time_W,
    const float* __restrict__ time_b,
    const float* __restrict__ W1,
    const float* __restrict__ b1, const float* __restrict__ W2,
    const float* __restrict__ b2, const float* __restrict__ h_new,
    float* __restrict__ prob)
{
    __shared__ float comb[16][P_IN];
    __shared__ float part[4][2][4];

    const int tid  = threadIdx.x;
    const int g    = tid >> 6;
    const int j    = tid & 63;
    const int base = blockIdx.x * 16;

    for (int idx = tid; idx < 16 * P_IN; idx += 256) {
        int le  = idx / P_IN;
        int off = idx - le * P_IN;
        int b = base + le;
        float v;
        if (off < 128) {
            v = h_new[(size_t)src_ids[b] * H + off];
        } else if (off < 256) {
            v = h_new[(size_t)dst_ids[b] * H + (off - 128)];
        } else {
            int e = etype_ids[b];
            if (off < 288)       v = eid_emb[e * 32 + (off - 256)];
            else if (off < 304)  { int c0 = ecat_codes[e];
                                   v = ecat_emb[c0 * 16 + (off - 288)]; }
            else if (off < 320)  { int c1 = ecat_codes[N_ETYPES + e];
                                   v = ecat_emb[(32 + c1) * 16 + (off - 304)]; }
            else                 { int k = off - 320;
                                   v = fmaf(t_rel[b], time_W[k], time_b[k]); }
        }
        comb[le][off] = v;
    }
    __syncthreads();

    float bj = b1[j];
    float h0 = bj, h1 = bj, h2 = bj, h3 = bj;
    const float* c0 = comb[g * 4 + 0];
    const float* c1 = comb[g * 4 + 1];
    const float* c2 = comb[g * 4 + 2];
    const float* c3 = comb[g * 4 + 3];
    #pragma unroll 4
    for (int i = 0; i < P_IN; ++i) {
        float w = W1[i * P_HID + j];
        h0 = fmaf(c0[i], w, h0);
        h1 = fmaf(c1[i], w, h1);
        h2 = fmaf(c2[i], w, h2);
        h3 = fmaf(c3[i], w, h3);
    }
    float w2 = W2[j];
    float v0 = fmaxf(h0, 0.0f) * w2;
    float v1 = fmaxf(h1, 0.0f) * w2;
    float v2 = fmaxf(h2, 0.0f) * w2;
    float v3 = fmaxf(h3, 0.0f) * w2;

    #pragma unroll
    for (int off = 16; off > 0; off >>= 1) {
        v0 += __shfl_down_sync(0xffffffffu, v0, off);
        v1 += __shfl_down_sync(0xffffffffu, v1, off);
        v2 += __shfl_down_sync(0xffffffffu, v2, off);
        v3 += __shfl_down_sync(0xffffffffu, v3, off);
    }
    if ((j & 31) == 0) {
        int wh = j >> 5;
        part[g][wh][0] = v0; part[g][wh][1] = v1;
        part[g][wh][2] = v2; part[g][wh][3] = v3;
    }
    __syncthreads();
    if (j < 4) {
        float zsum = part[g][0][j] + part[g][1][j] + b2[0];
        prob[base + g * 4 + j] = 1.0f / (1.0f + expf(-zsum));
    }
}

// ---------------------------------------------------------------------------
extern "C" void kernel_launch(void* const* d_in, const int* in_sizes, int n_in,
                              void* d_out, int out_size)
{
    const int*   src_ids    = (const int*)  d_in[0];
    const int*   dst_ids    = (const int*)  d_in[1];
    const int*   etype_ids  = (const int*)  d_in[2];
    const float* t_rel      = (const float*)d_in[3];
    const float* node_cont  = (const float*)d_in[4];
    const int*   ncat_codes = (const int*)  d_in[5];
    const int*   ecat_codes = (const int*)  d_in[6];
    /* d_in[7] = edge_index, unused */
    const float* h_prev     = (const float*)d_in[8];
    const float* c_prev     = (const float*)d_in[9];
    const float* ncat_emb   = (const float*)d_in[10];
    const float* eid_emb    = (const float*)d_in[11];
    const float* ecat_emb   = (const float*)d_in[12];
    const float* time_W     = (const float*)d_in[13];
    const float* time_b     = (const float*)d_in[14];
    const float* Wx         = (const float*)d_in[15];
    const float* Wh         = (const float*)d_in[16];
    const float* b_gate     = (const float*)d_in[17];
    const float* w_c        = (const float*)d_in[18];
    const float* W1         = (const float*)d_in[19];
    const float* b1         = (const float*)d_in[20];
    const float* W2         = (const float*)d_in[21];
    const float* b2         = (const float*)d_in[22];

    float* out   = (float*)d_out;
    float* prob  = out;
    float* h_new = out + B_EDGES;
    float* c_new = out + B_EDGES + (size_t)N_NODES * H;

    cudaFuncSetAttribute(node_update_mma_kernel,
                         cudaFuncAttributeMaxDynamicSharedMemorySize, SMEM_BYTES);

    prep_weights_kernel<<<(KSLICES * 64 * 64 + 255) / 256, 256>>>(Wx, Wh, b_gate);

    node_update_mma_kernel<<<M_TILES * 2, 512, SMEM_BYTES>>>(
        node_cont, ncat_codes, ncat_emb, h_prev, c_prev, w_c, h_new, c_new);

    edge_mlp_kernel<<<B_EDGES / 16, 256>>>(
        src_ids, dst_ids, etype_ids, t_rel,
        ecat_codes, eid_emb, ecat_emb, time_W, time_b,
        W1, b1, W2, b2, h_new, prob);
}

// round 8
// speedup vs baseline: 1.4075x; 1.2464x over previous
#include <cuda_runtime.h>
#include <cuda_fp16.h>
#include <math.h>
#include <stdint.h>

#define N_NODES 150000
#define N_ETYPES 1000
#define B_EDGES 16384
#define H 128
#define P_IN 336
#define P_HID 64

// Node GEMM: z[150016, 512] = A_ext[150016, 384] @ W_ext[384, 512]  (fp16 2-pass)
// A_ext = [A_hi | A_lo]; W reused for both passes (only W quantization error ~1e-4)
// N layout: n = 4*h + g (gates interleaved)
#define KTILES 24
#define KSLICES 12
#define MTILE 128
#define M_TILES 1172           // ceil(150000/128); 150016 padded rows

// B fragments, uint4 per lane: [sl(12)][npair(32)][lane(32)] uint4
__device__ __align__(16) uint4 g_Wpack4[KSLICES * 32 * 32];
// A fragments: [mt(1172)][kt(24)][sub(8)][lane(32)] uint4  (115 MB)
__device__ __align__(16) uint4 g_Aext[(size_t)M_TILES * 24 * 8 * 32];
// z scratch: [150016][512] fp32 (307 MB)
__device__ float g_z[(size_t)M_TILES * 128 * 512];

// ---------------------------------------------------------------------------
__device__ __forceinline__ unsigned short f2h_bits(float f) {
    return __half_as_ushort(__float2half_rn(f));
}
__device__ __forceinline__ float h_val(unsigned short u) {
    return __half2float(__ushort_as_half(u));
}
__device__ __forceinline__ uint32_t pack_hi2(float a, float b) {
    return (uint32_t)f2h_bits(a) | ((uint32_t)f2h_bits(b) << 16);
}
__device__ __forceinline__ uint32_t pack_lo2(float a, float b) {
    unsigned short ha = f2h_bits(a), hb = f2h_bits(b);
    return (uint32_t)f2h_bits(a - h_val(ha)) | ((uint32_t)f2h_bits(b - h_val(hb)) << 16);
}
__device__ __forceinline__ float sigmoidf_(float x) { return 1.0f / (1.0f + expf(-x)); }

__device__ __forceinline__ void mma16816(float* c, const uint4 a, uint32_t bx, uint32_t by) {
    asm volatile("mma.sync.aligned.m16n8k16.row.col.f32.f16.f16.f32 "
        "{%0,%1,%2,%3}, {%4,%5,%6,%7}, {%8,%9}, {%0,%1,%2,%3};"
        : "+f"(c[0]), "+f"(c[1]), "+f"(c[2]), "+f"(c[3])
        : "r"(a.x), "r"(a.y), "r"(a.z), "r"(a.w), "r"(bx), "r"(by));
}

// ---------------------------------------------------------------------------
// Kernel 1: pack W into B-fragment uint4 layout.
// u32 = {W[k0][n], W[k0+1][n]} fp16; uint4 pairs two n8 blocks.
// ---------------------------------------------------------------------------
__device__ __forceinline__ unsigned short w_bits(
    int k, int n, const float* Wx, const float* Wh, const float* bg)
{
    int g = n & 3, h = n >> 2;
    float w;
    if (k < 128)       w = Wh[(g * 128 + k) * 128 + h];
    else if (k < 178)  w = Wx[(g * 50 + (k - 128)) * 128 + h];
    else if (k == 178) w = bg[g * 128 + h];
    else               w = 0.0f;
    return f2h_bits(w);
}

__global__ void prep_weights_kernel(const float* __restrict__ Wx,
                                    const float* __restrict__ Wh,
                                    const float* __restrict__ bg)
{
    int idx = blockIdx.x * blockDim.x + threadIdx.x;   // u32 index
    if (idx >= KSLICES * 32 * 32 * 4) return;
    int r    = idx & 3;           // which u32 in uint4
    int lane = (idx >> 2) & 31;
    int np   = (idx >> 7) & 31;
    int sl   = idx >> 12;
    int n8   = np * 2 + (r >> 1);
    int whc  = r & 1;             // 0: k0..k1 ; 1: k0+8..k0+9
    int n    = n8 * 8 + (lane >> 2);
    int k0   = sl * 16 + (lane & 3) * 2 + whc * 8;
    unsigned short u0 = w_bits(k0,     n, Wx, Wh, bg);
    unsigned short u1 = w_bits(k0 + 1, n, Wx, Wh, bg);
    ((uint32_t*)g_Wpack4)[idx] = (uint32_t)u0 | ((uint32_t)u1 << 16);
}

// ---------------------------------------------------------------------------
// Kernel 2: build A_ext in mma A-fragment order.
// One CTA per mtile (256 thr = 8 warps). Warp w owns 16-row subtile w.
// iter sl=0..11 emits BOTH hi (kt=sl) and lo (kt=sl+12) fragments.
// ---------------------------------------------------------------------------
__global__ void __launch_bounds__(256) build_a_kernel(
    const float* __restrict__ node_cont,
    const int*   __restrict__ ncat_codes,
    const float* __restrict__ ncat_emb,
    const float* __restrict__ h_prev)
{
    __shared__ float xs[128][64];     // feature cols k=128..191 (50 real + bias + pad)

    const int tid  = threadIdx.x;
    const int lane = tid & 31;
    const int w    = tid >> 5;        // warp = row subtile
    const int mt   = blockIdx.x;
    const int n0m  = mt * MTILE;

    // stage features
    for (int it = 0; it < 32; ++it) {
        int e = tid + it * 256;       // 8192
        int row = e >> 6, kr = e & 63;
        int node = n0m + row;
        float v = 0.0f;
        if (node < N_NODES) {
            if (kr < 2)        v = node_cont[node * 2 + kr];
            else if (kr < 50)  {
                int j = (kr - 2) >> 4, kd = (kr - 2) & 15;
                int code = ncat_codes[j * N_NODES + node];
                v = ncat_emb[(j * 64 + code) * 16 + kd];
            } else if (kr == 50) v = 1.0f;
        }
        xs[row][kr] = v;
    }
    __syncthreads();

    const int gr   = lane >> 2;
    const int kc   = (lane & 3) * 2;
    const int r0   = w * 16 + gr;         // local rows
    const int r1   = r0 + 8;
    const int nd0  = n0m + r0;
    const int nd1  = n0m + r1;

    #pragma unroll 2
    for (int sl = 0; sl < 12; ++sl) {
        int kg = sl * 16 + kc;            // k for a0/a1; a2/a3 use kg+8
        float2 s00, s01, s10, s11;        // [row][kblock]
        if (kg < 128) {
            s00 = (nd0 < N_NODES) ? *(const float2*)(h_prev + (size_t)nd0 * H + kg)
                                  : make_float2(0.f, 0.f);
            s10 = (nd1 < N_NODES) ? *(const float2*)(h_prev + (size_t)nd1 * H + kg)
                                  : make_float2(0.f, 0.f);
        } else {
            s00 = *(const float2*)&xs[r0][kg - 128];
            s10 = *(const float2*)&xs[r1][kg - 128];
        }
        int kg8 = kg + 8;
        if (kg8 < 128) {
            s01 = (nd0 < N_NODES) ? *(const float2*)(h_prev + (size_t)nd0 * H + kg8)
                                  : make_float2(0.f, 0.f);
            s11 = (nd1 < N_NODES) ? *(const float2*)(h_prev + (size_t)nd1 * H + kg8)
                                  : make_float2(0.f, 0.f);
        } else {
            s01 = *(const float2*)&xs[r0][kg8 - 128];
            s11 = *(const float2*)&xs[r1][kg8 - 128];
        }
        uint4 hi4, lo4;
        hi4.x = pack_hi2(s00.x, s00.y);  lo4.x = pack_lo2(s00.x, s00.y);
        hi4.y = pack_hi2(s10.x, s10.y);  lo4.y = pack_lo2(s10.x, s10.y);
        hi4.z = pack_hi2(s01.x, s01.y);  lo4.z = pack_lo2(s01.x, s01.y);
        hi4.w = pack_hi2(s11.x, s11.y);  lo4.w = pack_lo2(s11.x, s11.y);
        size_t base = (((size_t)mt * 24 + sl) * 8 + w) * 32 + lane;
        g_Aext[base]              = hi4;
        g_Aext[base + 12 * 8 * 32] = lo4;    // kt = sl + 12
    }
}

// ---------------------------------------------------------------------------
// Kernel 3: GEMM. No smem, no barriers. 256 thr = 8 warps (4m x 2n).
// CTA tile: 128 nodes x 128 cols. grid = M_TILES*4 (c = N chunk).
// ---------------------------------------------------------------------------
__global__ void __launch_bounds__(256) gemm_kernel()
{
    const int tid  = threadIdx.x;
    const int lane = tid & 31;
    const int wid  = tid >> 5;
    const int wm   = wid & 3;          // 0..3
    const int wn   = wid >> 2;         // 0..1
    const int mt   = blockIdx.x >> 2;
    const int c    = blockIdx.x & 3;

    float acc[2][8][4];
    #pragma unroll
    for (int mtt = 0; mtt < 2; ++mtt)
        #pragma unroll
        for (int nt = 0; nt < 8; ++nt)
            #pragma unroll
            for (int q = 0; q < 4; ++q) acc[mtt][nt][q] = 0.0f;

    const uint4* __restrict__ abase =
        g_Aext + ((size_t)mt * 24 * 8 + wm * 2) * 32 + lane;
    const uint4* __restrict__ bbase =
        g_Wpack4 + ((c * 2 + wn) * 4) * 32 + lane;

    #pragma unroll 2
    for (int kt = 0; kt < KTILES; ++kt) {
        int sl = (kt < KSLICES) ? kt : kt - KSLICES;
        uint4 a0 = abase[(size_t)(kt * 8 + 0) * 32];
        uint4 a1 = abase[(size_t)(kt * 8 + 1) * 32];
        uint4 bb[4];
        #pragma unroll
        for (int j = 0; j < 4; ++j)
            bb[j] = bbase[(size_t)(sl * 32 + j) * 32];
        #pragma unroll
        for (int j = 0; j < 4; ++j) {
            mma16816(acc[0][2*j],   a0, bb[j].x, bb[j].y);
            mma16816(acc[1][2*j],   a1, bb[j].x, bb[j].y);
            mma16816(acc[0][2*j+1], a0, bb[j].z, bb[j].w);
            mma16816(acc[1][2*j+1], a1, bb[j].z, bb[j].w);
        }
    }

    // store z directly (fire-and-forget)
    const int gr = lane >> 2, qq = lane & 3;
    const int colbase = (c * 2 + wn) * 64 + qq * 2;
    #pragma unroll
    for (int mtt = 0; mtt < 2; ++mtt) {
        size_t row0 = (size_t)mt * 128 + wm * 32 + mtt * 16 + gr;
        #pragma unroll
        for (int nt = 0; nt < 8; ++nt) {
            int col = colbase + nt * 8;
            *(float2*)&g_z[row0 * 512 + col] =
                make_float2(acc[mtt][nt][0], acc[mtt][nt][1]);
            *(float2*)&g_z[(row0 + 8) * 512 + col] =
                make_float2(acc[mtt][nt][2], acc[mtt][nt][3]);
        }
    }
}

// ---------------------------------------------------------------------------
// Kernel 4: LSTM epilogue. 256 thr = 8 nodes/block, lane = h-quad.
// ---------------------------------------------------------------------------
__global__ void __launch_bounds__(256) lstm_kernel(
    const float* __restrict__ c_prev,
    const float* __restrict__ w_c,
    float* __restrict__ h_new,
    float* __restrict__ c_new)
{
    const int lane = threadIdx.x & 31;
    const int nl   = threadIdx.x >> 5;
    const size_t node = (size_t)blockIdx.x * 8 + nl;   // grid 18750 -> exact

    const float4* zq = (const float4*)(g_z + node * 512);
    float4 wi = ((const float4*)w_c)[lane];
    float4 wf = ((const float4*)w_c)[32 + lane];
    float4 wo = ((const float4*)w_c)[64 + lane];
    float4 cp = ((const float4*)(c_prev + node * H))[lane];
    float cc[4] = {cp.x, cp.y, cp.z, cp.w};
    float wiv[4] = {wi.x, wi.y, wi.z, wi.w};
    float wfv[4] = {wf.x, wf.y, wf.z, wf.w};
    float wov[4] = {wo.x, wo.y, wo.z, wo.w};
    float cn[4], hn[4];
    #pragma unroll
    for (int j = 0; j < 4; ++j) {
        float4 z = zq[lane * 4 + j];      // gates g0..g3 for h = lane*4+j
        float cv = cc[j];
        float ig = sigmoidf_(z.x + wiv[j] * cv);
        float fg = sigmoidf_(z.y + wfv[j] * cv);
        float tg = tanhf(z.z);
        float cnv = fg * cv + ig * tg;
        float og = sigmoidf_(z.w + wov[j] * cnv);
        cn[j] = cnv;
        hn[j] = og * tanhf(cnv);
    }
    ((float4*)(c_new + node * H))[lane] = make_float4(cn[0], cn[1], cn[2], cn[3]);
    ((float4*)(h_new + node * H))[lane] = make_float4(hn[0], hn[1], hn[2], hn[3]);
}

// ---------------------------------------------------------------------------
// Kernel 5: Edge MLP (unchanged).
// ---------------------------------------------------------------------------
__global__ void __launch_bounds__(256) edge_mlp_kernel(
    const int*   __restrict__ src_ids, const int* __restrict__ dst_ids,
    const int*   __restrict__ etype_ids, const float* __restrict__ t_rel,
    const int*   __restrict__ ecat_codes, const float* __restrict__ eid_emb,
    const float* __restrict__ ecat_emb, const float* __restrict__ time_W,
    const float* __restrict__ time_b,
    const float* __restrict__ W1,
    const float* __restrict__ b1, const float* __restrict__ W2,
    const float* __restrict__ b2, const float* __restrict__ h_new,
    float* __restrict__ prob)
{
    __shared__ float comb[16][P_IN];
    __shared__ float part[4][2][4];

    const int tid  = threadIdx.x;
    const int g    = tid >> 6;
    const int j    = tid & 63;
    const int base = blockIdx.x * 16;

    for (int idx = tid; idx < 16 * P_IN; idx += 256) {
        int le  = idx / P_IN;
        int off = idx - le * P_IN;
        int b = base + le;
        float v;
        if (off < 128) {
            v = h_new[(size_t)src_ids[b] * H + off];
        } else if (off < 256) {
            v = h_new[(size_t)dst_ids[b] * H + (off - 128)];
        } else {
            int e = etype_ids[b];
            if (off < 288)       v = eid_emb[e * 32 + (off - 256)];
            else if (off < 304)  { int c0 = ecat_codes[e];
                                   v = ecat_emb[c0 * 16 + (off - 288)]; }
            else if (off < 320)  { int c1 = ecat_codes[N_ETYPES + e];
                                   v = ecat_emb[(32 + c1) * 16 + (off - 304)]; }
            else                 { int k = off - 320;
                                   v = fmaf(t_rel[b], time_W[k], time_b[k]); }
        }
        comb[le][off] = v;
    }
    __syncthreads();

    float bj = b1[j];
    float h0 = bj, h1 = bj, h2 = bj, h3 = bj;
    const float* c0 = comb[g * 4 + 0];
    const float* c1 = comb[g * 4 + 1];
    const float* c2 = comb[g * 4 + 2];
    const float* c3 = comb[g * 4 + 3];
    #pragma unroll 4
    for (int i = 0; i < P_IN; ++i) {
        float w = W1[i * P_HID + j];
        h0 = fmaf(c0[i], w, h0);
        h1 = fmaf(c1[i], w, h1);
        h2 = fmaf(c2[i], w, h2);
        h3 = fmaf(c3[i], w, h3);
    }
    float w2 = W2[j];
    float v0 = fmaxf(h0, 0.0f) * w2;
    float v1 = fmaxf(h1, 0.0f) * w2;
    float v2 = fmaxf(h2, 0.0f) * w2;
    float v3 = fmaxf(h3, 0.0f) * w2;

    #pragma unroll
    for (int off = 16; off > 0; off >>= 1) {
        v0 += __shfl_down_sync(0xffffffffu, v0, off);
        v1 += __shfl_down_sync(0xffffffffu, v1, off);
        v2 += __shfl_down_sync(0xffffffffu, v2, off);
        v3 += __shfl_down_sync(0xffffffffu, v3, off);
    }
    if ((j & 31) == 0) {
        int wh = j >> 5;
        part[g][wh][0] = v0; part[g][wh][1] = v1;
        part[g][wh][2] = v2; part[g][wh][3] = v3;
    }
    __syncthreads();
    if (j < 4) {
        float zsum = part[g][0][j] + part[g][1][j] + b2[0];
        prob[base + g * 4 + j] = 1.0f / (1.0f + expf(-zsum));
    }
}

// ---------------------------------------------------------------------------
extern "C" void kernel_launch(void* const* d_in, const int* in_sizes, int n_in,
                              void* d_out, int out_size)
{
    const int*   src_ids    = (const int*)  d_in[0];
    const int*   dst_ids    = (const int*)  d_in[1];
    const int*   etype_ids  = (const int*)  d_in[2];
    const float* t_rel      = (const float*)d_in[3];
    const float* node_cont  = (const float*)d_in[4];
    const int*   ncat_codes = (const int*)  d_in[5];
    const int*   ecat_codes = (const int*)  d_in[6];
    /* d_in[7] = edge_index, unused */
    const float* h_prev     = (const float*)d_in[8];
    const float* c_prev     = (const float*)d_in[9];
    const float* ncat_emb   = (const float*)d_in[10];
    const float* eid_emb    = (const float*)d_in[11];
    const float* ecat_emb   = (const float*)d_in[12];
    const float* time_W     = (const float*)d_in[13];
    const float* time_b     = (const float*)d_in[14];
    const float* Wx         = (const float*)d_in[15];
    const float* Wh         = (const float*)d_in[16];
    const float* b_gate     = (const float*)d_in[17];
    const float* w_c        = (const float*)d_in[18];
    const float* W1         = (const float*)d_in[19];
    const float* b1         = (const float*)d_in[20];
    const float* W2         = (const float*)d_in[21];
    const float* b2         = (const float*)d_in[22];

    float* out   = (float*)d_out;
    float* prob  = out;
    float* h_new = out + B_EDGES;
    float* c_new = out + B_EDGES + (size_t)N_NODES * H;

    prep_weights_kernel<<<(KSLICES * 32 * 32 * 4 + 255) / 256, 256>>>(Wx, Wh, b_gate);

    build_a_kernel<<<M_TILES, 256>>>(node_cont, ncat_codes, ncat_emb, h_prev);

    gemm_kernel<<<M_TILES * 4, 256>>>();

    lstm_kernel<<<N_NODES / 8, 256>>>(c_prev, w_c, h_new, c_new);

    edge_mlp_kernel<<<B_EDGES / 16, 256>>>(
        src_ids, dst_ids, etype_ids, t_rel,
        ecat_codes, eid_emb, ecat_emb, time_W, time_b,
        W1, b1, W2, b2, h_new, prob);
}

// round 9
// speedup vs baseline: 1.8188x; 1.2922x over previous
#include <cuda_runtime.h>
#include <cuda_fp16.h>
#include <math.h>
#include <stdint.h>

#define N_NODES 150000
#define N_ETYPES 1000
#define B_EDGES 16384
#define H 128
#define P_IN 336
#define P_HID 64

// Node GEMM: z[150016, 512] = A_ext[150016, 384] @ W_ext[384, 512]  (fp16 2-pass)
// A_ext = [A_hi | A_lo]; W reused for both passes (only W quantization error ~1e-4)
// Column permutation (physical fragment col p -> logical gate/h):
//   g = (p&1) | (((p>>3)&1)<<1),  h = ((p>>1)&3) | ((p>>4)<<2)
// so each GEMM thread holds all 4 gates of one (row,h) cell -> fused LSTM epilogue.
#define KTILES 24
#define KSLICES 12
#define MTILE 128
#define M_TILES 1172           // ceil(150000/128); 150016 padded rows

// B fragments, uint4 per lane: [sl(12)][npair(32)][lane(32)] uint4
__device__ __align__(16) uint4 g_Wpack4[KSLICES * 32 * 32];
// A fragments: [mt(1172)][kt(24)][sub(8)][lane(32)] uint4  (115 MB)
__device__ __align__(16) uint4 g_Aext[(size_t)M_TILES * 24 * 8 * 32];

// ---------------------------------------------------------------------------
__device__ __forceinline__ unsigned short f2h_bits(float f) {
    return __half_as_ushort(__float2half_rn(f));
}
__device__ __forceinline__ float h_val(unsigned short u) {
    return __half2float(__ushort_as_half(u));
}
__device__ __forceinline__ uint32_t pack_hi2(float a, float b) {
    return (uint32_t)f2h_bits(a) | ((uint32_t)f2h_bits(b) << 16);
}
__device__ __forceinline__ uint32_t pack_lo2(float a, float b) {
    unsigned short ha = f2h_bits(a), hb = f2h_bits(b);
    return (uint32_t)f2h_bits(a - h_val(ha)) | ((uint32_t)f2h_bits(b - h_val(hb)) << 16);
}
// fast-but-accurate (~2^-22 rel) nonlinearities via MUFU.EX2 / MUFU.RCP
__device__ __forceinline__ float sigf(float x) {
    return __fdividef(1.0f, 1.0f + __expf(-x));
}
__device__ __forceinline__ float tanhf_fast(float x) {
    return fmaf(-2.0f, __fdividef(1.0f, 1.0f + __expf(2.0f * x)), 1.0f);
}
__device__ __forceinline__ float sigmoidf_(float x) { return 1.0f / (1.0f + expf(-x)); }

__device__ __forceinline__ void mma16816(float* c, const uint4 a, uint32_t bx, uint32_t by) {
    asm volatile("mma.sync.aligned.m16n8k16.row.col.f32.f16.f16.f32 "
        "{%0,%1,%2,%3}, {%4,%5,%6,%7}, {%8,%9}, {%0,%1,%2,%3};"
        : "+f"(c[0]), "+f"(c[1]), "+f"(c[2]), "+f"(c[3])
        : "r"(a.x), "r"(a.y), "r"(a.z), "r"(a.w), "r"(bx), "r"(by));
}

// ---------------------------------------------------------------------------
// Kernel 1: pack W into B-fragment uint4 layout with gate/h bit permutation.
// ---------------------------------------------------------------------------
__device__ __forceinline__ unsigned short w_bits_gh(
    int k, int g, int h, const float* Wx, const float* Wh, const float* bg)
{
    float w;
    if (k < 128)       w = Wh[(g * 128 + k) * 128 + h];
    else if (k < 178)  w = Wx[(g * 50 + (k - 128)) * 128 + h];
    else if (k == 178) w = bg[g * 128 + h];
    else               w = 0.0f;
    return f2h_bits(w);
}

__global__ void prep_weights_kernel(const float* __restrict__ Wx,
                                    const float* __restrict__ Wh,
                                    const float* __restrict__ bg)
{
    int idx = blockIdx.x * blockDim.x + threadIdx.x;   // u32 index
    if (idx >= KSLICES * 32 * 32 * 4) return;
    int r    = idx & 3;           // which u32 in uint4
    int lane = (idx >> 2) & 31;
    int np   = (idx >> 7) & 31;
    int sl   = idx >> 12;
    int n8   = np * 2 + (r >> 1);
    int whc  = r & 1;             // 0: k0..k1 ; 1: k0+8..k0+9
    int p    = n8 * 8 + (lane >> 2);        // physical col 0..511
    int g    = (p & 1) | (((p >> 3) & 1) << 1);
    int h    = ((p >> 1) & 3) | ((p >> 4) << 2);
    int k0   = sl * 16 + (lane & 3) * 2 + whc * 8;
    unsigned short u0 = w_bits_gh(k0,     g, h, Wx, Wh, bg);
    unsigned short u1 = w_bits_gh(k0 + 1, g, h, Wx, Wh, bg);
    ((uint32_t*)g_Wpack4)[idx] = (uint32_t)u0 | ((uint32_t)u1 << 16);
}

// ---------------------------------------------------------------------------
// Kernel 2: build A_ext in mma A-fragment order (unchanged from R8).
// ---------------------------------------------------------------------------
__global__ void __launch_bounds__(256) build_a_kernel(
    const float* __restrict__ node_cont,
    const int*   __restrict__ ncat_codes,
    const float* __restrict__ ncat_emb,
    const float* __restrict__ h_prev)
{
    __shared__ float xs[128][64];

    const int tid  = threadIdx.x;
    const int lane = tid & 31;
    const int w    = tid >> 5;
    const int mt   = blockIdx.x;
    const int n0m  = mt * MTILE;

    for (int it = 0; it < 32; ++it) {
        int e = tid + it * 256;
        int row = e >> 6, kr = e & 63;
        int node = n0m + row;
        float v = 0.0f;
        if (node < N_NODES) {
            if (kr < 2)        v = node_cont[node * 2 + kr];
            else if (kr < 50)  {
                int j = (kr - 2) >> 4, kd = (kr - 2) & 15;
                int code = ncat_codes[j * N_NODES + node];
                v = ncat_emb[(j * 64 + code) * 16 + kd];
            } else if (kr == 50) v = 1.0f;
        }
        xs[row][kr] = v;
    }
    __syncthreads();

    const int gr   = lane >> 2;
    const int kc   = (lane & 3) * 2;
    const int r0   = w * 16 + gr;
    const int r1   = r0 + 8;
    const int nd0  = n0m + r0;
    const int nd1  = n0m + r1;

    #pragma unroll 2
    for (int sl = 0; sl < 12; ++sl) {
        int kg = sl * 16 + kc;
        float2 s00, s01, s10, s11;
        if (kg < 128) {
            s00 = (nd0 < N_NODES) ? *(const float2*)(h_prev + (size_t)nd0 * H + kg)
                                  : make_float2(0.f, 0.f);
            s10 = (nd1 < N_NODES) ? *(const float2*)(h_prev + (size_t)nd1 * H + kg)
                                  : make_float2(0.f, 0.f);
        } else {
            s00 = *(const float2*)&xs[r0][kg - 128];
            s10 = *(const float2*)&xs[r1][kg - 128];
        }
        int kg8 = kg + 8;
        if (kg8 < 128) {
            s01 = (nd0 < N_NODES) ? *(const float2*)(h_prev + (size_t)nd0 * H + kg8)
                                  : make_float2(0.f, 0.f);
            s11 = (nd1 < N_NODES) ? *(const float2*)(h_prev + (size_t)nd1 * H + kg8)
                                  : make_float2(0.f, 0.f);
        } else {
            s01 = *(const float2*)&xs[r0][kg8 - 128];
            s11 = *(const float2*)&xs[r1][kg8 - 128];
        }
        uint4 hi4, lo4;
        hi4.x = pack_hi2(s00.x, s00.y);  lo4.x = pack_lo2(s00.x, s00.y);
        hi4.y = pack_hi2(s10.x, s10.y);  lo4.y = pack_lo2(s10.x, s10.y);
        hi4.z = pack_hi2(s01.x, s01.y);  lo4.z = pack_lo2(s01.x, s01.y);
        hi4.w = pack_hi2(s11.x, s11.y);  lo4.w = pack_lo2(s11.x, s11.y);
        size_t base = (((size_t)mt * 24 + sl) * 8 + w) * 32 + lane;
        g_Aext[base]               = hi4;
        g_Aext[base + 12 * 8 * 32] = lo4;    // kt = sl + 12
    }
}

// ---------------------------------------------------------------------------
// Kernel 3: GEMM + fused LSTM epilogue. No smem, no barriers.
// 256 thr = 8 warps (4m x 2n). CTA tile: 128 nodes x 128 cols (= 32 h).
// grid = M_TILES*4 (c = N chunk).
// ---------------------------------------------------------------------------
__global__ void __launch_bounds__(256, 2) gemm_lstm_kernel(
    const float* __restrict__ c_prev,
    const float* __restrict__ w_c,
    float* __restrict__ h_new,
    float* __restrict__ c_new)
{
    const int tid  = threadIdx.x;
    const int lane = tid & 31;
    const int wid  = tid >> 5;
    const int wm   = wid & 3;          // 0..3
    const int wn   = wid >> 2;         // 0..1
    const int mt   = blockIdx.x >> 2;
    const int c    = blockIdx.x & 3;

    float acc[2][8][4];
    #pragma unroll
    for (int mtt = 0; mtt < 2; ++mtt)
        #pragma unroll
        for (int nt = 0; nt < 8; ++nt)
            #pragma unroll
            for (int q = 0; q < 4; ++q) acc[mtt][nt][q] = 0.0f;

    const uint4* __restrict__ abase =
        g_Aext + ((size_t)mt * 24 * 8 + wm * 2) * 32 + lane;
    const uint4* __restrict__ bbase =
        g_Wpack4 + ((c * 2 + wn) * 4) * 32 + lane;

    #pragma unroll 2
    for (int kt = 0; kt < KTILES; ++kt) {
        int sl = (kt < KSLICES) ? kt : kt - KSLICES;
        uint4 a0 = abase[(size_t)(kt * 8 + 0) * 32];
        uint4 a1 = abase[(size_t)(kt * 8 + 1) * 32];
        uint4 bb[4];
        #pragma unroll
        for (int j = 0; j < 4; ++j)
            bb[j] = bbase[(size_t)(sl * 32 + j) * 32];
        #pragma unroll
        for (int j = 0; j < 4; ++j) {
            mma16816(acc[0][2*j],   a0, bb[j].x, bb[j].y);
            mma16816(acc[1][2*j],   a1, bb[j].x, bb[j].y);
            mma16816(acc[0][2*j+1], a0, bb[j].z, bb[j].w);
            mma16816(acc[1][2*j+1], a1, bb[j].z, bb[j].w);
        }
    }

    // ---- fused LSTM epilogue.
    // acc[mtt][2*hh][0..1] = (z_g0, z_g1), acc[mtt][2*hh+1][0..1] = (z_g2, z_g3)
    // for (row = wm*32+mtt*16+gr, h = (c*2+wn)*16 + hh*4 + qq); q 2..3 = row+8.
    const int gr = lane >> 2, qq = lane & 3;
    const int C  = c * 2 + wn;
    #pragma unroll
    for (int hh = 0; hh < 4; ++hh) {
        const int h = C * 16 + hh * 4 + qq;
        const float wi = w_c[h];
        const float wf = w_c[128 + h];
        const float wo = w_c[256 + h];
        #pragma unroll
        for (int mtt = 0; mtt < 2; ++mtt) {
            size_t node0 = (size_t)mt * 128 + wm * 32 + mtt * 16 + gr;
            #pragma unroll
            for (int half = 0; half < 2; ++half) {
                size_t node = node0 + half * 8;
                if (node < N_NODES) {
                    int qb = half * 2;
                    float z0 = acc[mtt][2*hh][qb],   z1 = acc[mtt][2*hh][qb+1];
                    float z2 = acc[mtt][2*hh+1][qb], z3 = acc[mtt][2*hh+1][qb+1];
                    size_t off = node * H + h;
                    float cv = c_prev[off];
                    float ig = sigf(z0 + wi * cv);
                    float fg = sigf(z1 + wf * cv);
                    float tg = tanhf_fast(z2);
                    float cn = fg * cv + ig * tg;
                    float og = sigf(z3 + wo * cn);
                    c_new[off] = cn;
                    h_new[off] = og * tanhf_fast(cn);
                }
            }
        }
    }
}

// ---------------------------------------------------------------------------
// Kernel 4: Edge MLP (unchanged).
// ---------------------------------------------------------------------------
__global__ void __launch_bounds__(256) edge_mlp_kernel(
    const int*   __restrict__ src_ids, const int* __restrict__ dst_ids,
    const int*   __restrict__ etype_ids, const float* __restrict__ t_rel,
    const int*   __restrict__ ecat_codes, const float* __restrict__ eid_emb,
    const float* __restrict__ ecat_emb, const float* __restrict__ time_W,
    const float* __restrict__ time_b,
    const float* __restrict__ W1,
    const float* __restrict__ b1, const float* __restrict__ W2,
    const float* __restrict__ b2, const float* __restrict__ h_new,
    float* __restrict__ prob)
{
    __shared__ float comb[16][P_IN];
    __shared__ float part[4][2][4];

    const int tid  = threadIdx.x;
    const int g    = tid >> 6;
    const int j    = tid & 63;
    const int base = blockIdx.x * 16;

    for (int idx = tid; idx < 16 * P_IN; idx += 256) {
        int le  = idx / P_IN;
        int off = idx - le * P_IN;
        int b = base + le;
        float v;
        if (off < 128) {
            v = h_new[(size_t)src_ids[b] * H + off];
        } else if (off < 256) {
            v = h_new[(size_t)dst_ids[b] * H + (off - 128)];
        } else {
            int e = etype_ids[b];
            if (off < 288)       v = eid_emb[e * 32 + (off - 256)];
            else if (off < 304)  { int c0 = ecat_codes[e];
                                   v = ecat_emb[c0 * 16 + (off - 288)]; }
            else if (off < 320)  { int c1 = ecat_codes[N_ETYPES + e];
                                   v = ecat_emb[(32 + c1) * 16 + (off - 304)]; }
            else                 { int k = off - 320;
                                   v = fmaf(t_rel[b], time_W[k], time_b[k]); }
        }
        comb[le][off] = v;
    }
    __syncthreads();

    float bj = b1[j];
    float h0 = bj, h1 = bj, h2 = bj, h3 = bj;
    const float* c0 = comb[g * 4 + 0];
    const float* c1 = comb[g * 4 + 1];
    const float* c2 = comb[g * 4 + 2];
    const float* c3 = comb[g * 4 + 3];
    #pragma unroll 4
    for (int i = 0; i < P_IN; ++i) {
        float w = W1[i * P_HID + j];
        h0 = fmaf(c0[i], w, h0);
        h1 = fmaf(c1[i], w, h1);
        h2 = fmaf(c2[i], w, h2);
        h3 = fmaf(c3[i], w, h3);
    }
    float w2 = W2[j];
    float v0 = fmaxf(h0, 0.0f) * w2;
    float v1 = fmaxf(h1, 0.0f) * w2;
    float v2 = fmaxf(h2, 0.0f) * w2;
    float v3 = fmaxf(h3, 0.0f) * w2;

    #pragma unroll
    for (int off = 16; off > 0; off >>= 1) {
        v0 += __shfl_down_sync(0xffffffffu, v0, off);
        v1 += __shfl_down_sync(0xffffffffu, v1, off);
        v2 += __shfl_down_sync(0xffffffffu, v2, off);
        v3 += __shfl_down_sync(0xffffffffu, v3, off);
    }
    if ((j & 31) == 0) {
        int wh = j >> 5;
        part[g][wh][0] = v0; part[g][wh][1] = v1;
        part[g][wh][2] = v2; part[g][wh][3] = v3;
    }
    __syncthreads();
    if (j < 4) {
        float zsum = part[g][0][j] + part[g][1][j] + b2[0];
        prob[base + g * 4 + j] = 1.0f / (1.0f + expf(-zsum));
    }
}

// ---------------------------------------------------------------------------
extern "C" void kernel_launch(void* const* d_in, const int* in_sizes, int n_in,
                              void* d_out, int out_size)
{
    const int*   src_ids    = (const int*)  d_in[0];
    const int*   dst_ids    = (const int*)  d_in[1];
    const int*   etype_ids  = (const int*)  d_in[2];
    const float* t_rel      = (const float*)d_in[3];
    const float* node_cont  = (const float*)d_in[4];
    const int*   ncat_codes = (const int*)  d_in[5];
    const int*   ecat_codes = (const int*)  d_in[6];
    /* d_in[7] = edge_index, unused */
    const float* h_prev     = (const float*)d_in[8];
    const float* c_prev     = (const float*)d_in[9];
    const float* ncat_emb   = (const float*)d_in[10];
    const float* eid_emb    = (const float*)d_in[11];
    const float* ecat_emb   = (const float*)d_in[12];
    const float* time_W     = (const float*)d_in[13];
    const float* time_b     = (const float*)d_in[14];
    const float* Wx         = (const float*)d_in[15];
    const float* Wh         = (const float*)d_in[16];
    const float* b_gate     = (const float*)d_in[17];
    const float* w_c        = (const float*)d_in[18];
    const float* W1         = (const float*)d_in[19];
    const float* b1         = (const float*)d_in[20];
    const float* W2         = (const float*)d_in[21];
    const float* b2         = (const float*)d_in[22];

    float* out   = (float*)d_out;
    float* prob  = out;
    float* h_new = out + B_EDGES;
    float* c_new = out + B_EDGES + (size_t)N_NODES * H;

    prep_weights_kernel<<<(KSLICES * 32 * 32 * 4 + 255) / 256, 256>>>(Wx, Wh, b_gate);

    build_a_kernel<<<M_TILES, 256>>>(node_cont, ncat_codes, ncat_emb, h_prev);

    gemm_lstm_kernel<<<M_TILES * 4, 256>>>(c_prev, w_c, h_new, c_new);

    edge_mlp_kernel<<<B_EDGES / 16, 256>>>(
        src_ids, dst_ids, etype_ids, t_rel,
        ecat_codes, eid_emb, ecat_emb, time_W, time_b,
        W1, b1, W2, b2, h_new, prob);
}

// round 10
// speedup vs baseline: 2.2965x; 1.2626x over previous
#include <cuda_runtime.h>
#include <cuda_fp16.h>
#include <math.h>
#include <stdint.h>

#define N_NODES 150000
#define N_ETYPES 1000
#define B_EDGES 16384
#define H 128
#define P_IN 336
#define P_HID 64

// Node GEMM: z[150016, 512] = A[150016, 192] @ W[192, 512]  (pure fp16, f32 accum)
// Single-pass fp16: A and W both quantized to fp16 (combined rel err ~2-3e-4 << 1e-3).
// Column permutation (physical fragment col p -> logical gate/h):
//   g = (p&1) | (((p>>3)&1)<<1),  h = ((p>>1)&3) | ((p>>4)<<2)
// so each GEMM thread holds all 4 gates of one (row,h) cell -> fused LSTM epilogue.
#define KTILES 12
#define MTILE 128
#define M_TILES 1172           // ceil(150000/128); 150016 padded rows

// B fragments, uint4 per lane: [sl(12)][npair(32)][lane(32)] uint4
__device__ __align__(16) uint4 g_Wpack4[KTILES * 32 * 32];
// A fragments: [mt(1172)][kt(12)][sub(8)][lane(32)] uint4  (57.6 MB)
__device__ __align__(16) uint4 g_Aext[(size_t)M_TILES * 12 * 8 * 32];

// ---------------------------------------------------------------------------
__device__ __forceinline__ unsigned short f2h_bits(float f) {
    return __half_as_ushort(__float2half_rn(f));
}
__device__ __forceinline__ uint32_t pack_h2(float a, float b) {
    return (uint32_t)f2h_bits(a) | ((uint32_t)f2h_bits(b) << 16);
}
// fast-but-accurate (~2^-22 rel) nonlinearities via MUFU.EX2 / MUFU.RCP
__device__ __forceinline__ float sigf(float x) {
    return __fdividef(1.0f, 1.0f + __expf(-x));
}
__device__ __forceinline__ float tanhf_fast(float x) {
    return fmaf(-2.0f, __fdividef(1.0f, 1.0f + __expf(2.0f * x)), 1.0f);
}

__device__ __forceinline__ void mma16816(float* c, const uint4 a, uint32_t bx, uint32_t by) {
    asm volatile("mma.sync.aligned.m16n8k16.row.col.f32.f16.f16.f32 "
        "{%0,%1,%2,%3}, {%4,%5,%6,%7}, {%8,%9}, {%0,%1,%2,%3};"
        : "+f"(c[0]), "+f"(c[1]), "+f"(c[2]), "+f"(c[3])
        : "r"(a.x), "r"(a.y), "r"(a.z), "r"(a.w), "r"(bx), "r"(by));
}

// ---------------------------------------------------------------------------
// Kernel 1: pack W into B-fragment uint4 layout with gate/h bit permutation.
// ---------------------------------------------------------------------------
__device__ __forceinline__ unsigned short w_bits_gh(
    int k, int g, int h, const float* Wx, const float* Wh, const float* bg)
{
    float w;
    if (k < 128)       w = Wh[(g * 128 + k) * 128 + h];
    else if (k < 178)  w = Wx[(g * 50 + (k - 128)) * 128 + h];
    else if (k == 178) w = bg[g * 128 + h];
    else               w = 0.0f;
    return f2h_bits(w);
}

__global__ void prep_weights_kernel(const float* __restrict__ Wx,
                                    const float* __restrict__ Wh,
                                    const float* __restrict__ bg)
{
    int idx = blockIdx.x * blockDim.x + threadIdx.x;   // u32 index
    if (idx >= KTILES * 32 * 32 * 4) return;
    int r    = idx & 3;           // which u32 in uint4
    int lane = (idx >> 2) & 31;
    int np   = (idx >> 7) & 31;
    int sl   = idx >> 12;
    int n8   = np * 2 + (r >> 1);
    int whc  = r & 1;             // 0: k0..k1 ; 1: k0+8..k0+9
    int p    = n8 * 8 + (lane >> 2);        // physical col 0..511
    int g    = (p & 1) | (((p >> 3) & 1) << 1);
    int h    = ((p >> 1) & 3) | ((p >> 4) << 2);
    int k0   = sl * 16 + (lane & 3) * 2 + whc * 8;
    unsigned short u0 = w_bits_gh(k0,     g, h, Wx, Wh, bg);
    unsigned short u1 = w_bits_gh(k0 + 1, g, h, Wx, Wh, bg);
    ((uint32_t*)g_Wpack4)[idx] = (uint32_t)u0 | ((uint32_t)u1 << 16);
}

// ---------------------------------------------------------------------------
// Kernel 2: build A in mma A-fragment order (single fp16 pass).
// ---------------------------------------------------------------------------
__global__ void __launch_bounds__(256) build_a_kernel(
    const float* __restrict__ node_cont,
    const int*   __restrict__ ncat_codes,
    const float* __restrict__ ncat_emb,
    const float* __restrict__ h_prev)
{
    __shared__ float xs[128][64];

    const int tid  = threadIdx.x;
    const int lane = tid & 31;
    const int w    = tid >> 5;
    const int mt   = blockIdx.x;
    const int n0m  = mt * MTILE;

    for (int it = 0; it < 32; ++it) {
        int e = tid + it * 256;
        int row = e >> 6, kr = e & 63;
        int node = n0m + row;
        float v = 0.0f;
        if (node < N_NODES) {
            if (kr < 2)        v = node_cont[node * 2 + kr];
            else if (kr < 50)  {
                int j = (kr - 2) >> 4, kd = (kr - 2) & 15;
                int code = ncat_codes[j * N_NODES + node];
                v = ncat_emb[(j * 64 + code) * 16 + kd];
            } else if (kr == 50) v = 1.0f;
        }
        xs[row][kr] = v;
    }
    __syncthreads();

    const int gr   = lane >> 2;
    const int kc   = (lane & 3) * 2;
    const int r0   = w * 16 + gr;
    const int r1   = r0 + 8;
    const int nd0  = n0m + r0;
    const int nd1  = n0m + r1;

    #pragma unroll 2
    for (int sl = 0; sl < 12; ++sl) {
        int kg = sl * 16 + kc;
        float2 s00, s01, s10, s11;
        if (kg < 128) {
            s00 = (nd0 < N_NODES) ? *(const float2*)(h_prev + (size_t)nd0 * H + kg)
                                  : make_float2(0.f, 0.f);
            s10 = (nd1 < N_NODES) ? *(const float2*)(h_prev + (size_t)nd1 * H + kg)
                                  : make_float2(0.f, 0.f);
        } else {
            s00 = *(const float2*)&xs[r0][kg - 128];
            s10 = *(const float2*)&xs[r1][kg - 128];
        }
        int kg8 = kg + 8;
        if (kg8 < 128) {
            s01 = (nd0 < N_NODES) ? *(const float2*)(h_prev + (size_t)nd0 * H + kg8)
                                  : make_float2(0.f, 0.f);
            s11 = (nd1 < N_NODES) ? *(const float2*)(h_prev + (size_t)nd1 * H + kg8)
                                  : make_float2(0.f, 0.f);
        } else {
            s01 = *(const float2*)&xs[r0][kg8 - 128];
            s11 = *(const float2*)&xs[r1][kg8 - 128];
        }
        uint4 hi4;
        hi4.x = pack_h2(s00.x, s00.y);
        hi4.y = pack_h2(s10.x, s10.y);
        hi4.z = pack_h2(s01.x, s01.y);
        hi4.w = pack_h2(s11.x, s11.y);
        g_Aext[(((size_t)mt * 12 + sl) * 8 + w) * 32 + lane] = hi4;
    }
}

// ---------------------------------------------------------------------------
// Kernel 3: GEMM + fused LSTM epilogue. No smem, no barriers.
// 256 thr = 8 warps (4m x 2n). CTA tile: 128 nodes x 128 cols (= 32 h).
// grid = M_TILES*4 (c = N chunk).
// ---------------------------------------------------------------------------
__global__ void __launch_bounds__(256, 2) gemm_lstm_kernel(
    const float* __restrict__ c_prev,
    const float* __restrict__ w_c,
    float* __restrict__ h_new,
    float* __restrict__ c_new)
{
    const int tid  = threadIdx.x;
    const int lane = tid & 31;
    const int wid  = tid >> 5;
    const int wm   = wid & 3;          // 0..3
    const int wn   = wid >> 2;         // 0..1
    const int mt   = blockIdx.x >> 2;
    const int c    = blockIdx.x & 3;

    float acc[2][8][4];
    #pragma unroll
    for (int mtt = 0; mtt < 2; ++mtt)
        #pragma unroll
        for (int nt = 0; nt < 8; ++nt)
            #pragma unroll
            for (int q = 0; q < 4; ++q) acc[mtt][nt][q] = 0.0f;

    const uint4* __restrict__ abase =
        g_Aext + ((size_t)mt * 12 * 8 + wm * 2) * 32 + lane;
    const uint4* __restrict__ bbase =
        g_Wpack4 + ((c * 2 + wn) * 4) * 32 + lane;

    #pragma unroll 2
    for (int kt = 0; kt < KTILES; ++kt) {
        uint4 a0 = abase[(size_t)(kt * 8 + 0) * 32];
        uint4 a1 = abase[(size_t)(kt * 8 + 1) * 32];
        uint4 bb[4];
        #pragma unroll
        for (int j = 0; j < 4; ++j)
            bb[j] = bbase[(size_t)(kt * 32 + j) * 32];
        #pragma unroll
        for (int j = 0; j < 4; ++j) {
            mma16816(acc[0][2*j],   a0, bb[j].x, bb[j].y);
            mma16816(acc[1][2*j],   a1, bb[j].x, bb[j].y);
            mma16816(acc[0][2*j+1], a0, bb[j].z, bb[j].w);
            mma16816(acc[1][2*j+1], a1, bb[j].z, bb[j].w);
        }
    }

    // ---- fused LSTM epilogue.
    // acc[mtt][2*hh][0..1] = (z_g0, z_g1), acc[mtt][2*hh+1][0..1] = (z_g2, z_g3)
    // for (row = wm*32+mtt*16+gr, h = (c*2+wn)*16 + hh*4 + qq); q 2..3 = row+8.
    const int gr = lane >> 2, qq = lane & 3;
    const int C  = c * 2 + wn;
    #pragma unroll
    for (int hh = 0; hh < 4; ++hh) {
        const int h = C * 16 + hh * 4 + qq;
        const float wi = w_c[h];
        const float wf = w_c[128 + h];
        const float wo = w_c[256 + h];
        #pragma unroll
        for (int mtt = 0; mtt < 2; ++mtt) {
            size_t node0 = (size_t)mt * 128 + wm * 32 + mtt * 16 + gr;
            #pragma unroll
            for (int half = 0; half < 2; ++half) {
                size_t node = node0 + half * 8;
                if (node < N_NODES) {
                    int qb = half * 2;
                    float z0 = acc[mtt][2*hh][qb],   z1 = acc[mtt][2*hh][qb+1];
                    float z2 = acc[mtt][2*hh+1][qb], z3 = acc[mtt][2*hh+1][qb+1];
                    size_t off = node * H + h;
                    float cv = c_prev[off];
                    float ig = sigf(z0 + wi * cv);
                    float fg = sigf(z1 + wf * cv);
                    float tg = tanhf_fast(z2);
                    float cn = fg * cv + ig * tg;
                    float og = sigf(z3 + wo * cn);
                    c_new[off] = cn;
                    h_new[off] = og * tanhf_fast(cn);
                }
            }
        }
    }
}

// ---------------------------------------------------------------------------
// Kernel 4: Edge MLP (unchanged).
// ---------------------------------------------------------------------------
__global__ void __launch_bounds__(256) edge_mlp_kernel(
    const int*   __restrict__ src_ids, const int* __restrict__ dst_ids,
    const int*   __restrict__ etype_ids, const float* __restrict__ t_rel,
    const int*   __restrict__ ecat_codes, const float* __restrict__ eid_emb,
    const float* __restrict__ ecat_emb, const float* __restrict__ time_W,
    const float* __restrict__ time_b,
    const float* __restrict__ W1,
    const float* __restrict__ b1, const float* __restrict__ W2,
    const float* __restrict__ b2, const float* __restrict__ h_new,
    float* __restrict__ prob)
{
    __shared__ float comb[16][P_IN];
    __shared__ float part[4][2][4];

    const int tid  = threadIdx.x;
    const int g    = tid >> 6;
    const int j    = tid & 63;
    const int base = blockIdx.x * 16;

    for (int idx = tid; idx < 16 * P_IN; idx += 256) {
        int le  = idx / P_IN;
        int off = idx - le * P_IN;
        int b = base + le;
        float v;
        if (off < 128) {
            v = h_new[(size_t)src_ids[b] * H + off];
        } else if (off < 256) {
            v = h_new[(size_t)dst_ids[b] * H + (off - 128)];
        } else {
            int e = etype_ids[b];
            if (off < 288)       v = eid_emb[e * 32 + (off - 256)];
            else if (off < 304)  { int c0 = ecat_codes[e];
                                   v = ecat_emb[c0 * 16 + (off - 288)]; }
            else if (off < 320)  { int c1 = ecat_codes[N_ETYPES + e];
                                   v = ecat_emb[(32 + c1) * 16 + (off - 304)]; }
            else                 { int k = off - 320;
                                   v = fmaf(t_rel[b], time_W[k], time_b[k]); }
        }
        comb[le][off] = v;
    }
    __syncthreads();

    float bj = b1[j];
    float h0 = bj, h1 = bj, h2 = bj, h3 = bj;
    const float* c0 = comb[g * 4 + 0];
    const float* c1 = comb[g * 4 + 1];
    const float* c2 = comb[g * 4 + 2];
    const float* c3 = comb[g * 4 + 3];
    #pragma unroll 4
    for (int i = 0; i < P_IN; ++i) {
        float w = W1[i * P_HID + j];
        h0 = fmaf(c0[i], w, h0);
        h1 = fmaf(c1[i], w, h1);
        h2 = fmaf(c2[i], w, h2);
        h3 = fmaf(c3[i], w, h3);
    }
    float w2 = W2[j];
    float v0 = fmaxf(h0, 0.0f) * w2;
    float v1 = fmaxf(h1, 0.0f) * w2;
    float v2 = fmaxf(h2, 0.0f) * w2;
    float v3 = fmaxf(h3, 0.0f) * w2;

    #pragma unroll
    for (int off = 16; off > 0; off >>= 1) {
        v0 += __shfl_down_sync(0xffffffffu, v0, off);
        v1 += __shfl_down_sync(0xffffffffu, v1, off);
        v2 += __shfl_down_sync(0xffffffffu, v2, off);
        v3 += __shfl_down_sync(0xffffffffu, v3, off);
    }
    if ((j & 31) == 0) {
        int wh = j >> 5;
        part[g][wh][0] = v0; part[g][wh][1] = v1;
        part[g][wh][2] = v2; part[g][wh][3] = v3;
    }
    __syncthreads();
    if (j < 4) {
        float zsum = part[g][0][j] + part[g][1][j] + b2[0];
        prob[base + g * 4 + j] = 1.0f / (1.0f + expf(-zsum));
    }
}

// ---------------------------------------------------------------------------
extern "C" void kernel_launch(void* const* d_in, const int* in_sizes, int n_in,
                              void* d_out, int out_size)
{
    const int*   src_ids    = (const int*)  d_in[0];
    const int*   dst_ids    = (const int*)  d_in[1];
    const int*   etype_ids  = (const int*)  d_in[2];
    const float* t_rel      = (const float*)d_in[3];
    const float* node_cont  = (const float*)d_in[4];
    const int*   ncat_codes = (const int*)  d_in[5];
    const int*   ecat_codes = (const int*)  d_in[6];
    /* d_in[7] = edge_index, unused */
    const float* h_prev     = (const float*)d_in[8];
    const float* c_prev     = (const float*)d_in[9];
    const float* ncat_emb   = (const float*)d_in[10];
    const float* eid_emb    = (const float*)d_in[11];
    const float* ecat_emb   = (const float*)d_in[12];
    const float* time_W     = (const float*)d_in[13];
    const float* time_b     = (const float*)d_in[14];
    const float* Wx         = (const float*)d_in[15];
    const float* Wh         = (const float*)d_in[16];
    const float* b_gate     = (const float*)d_in[17];
    const float* w_c        = (const float*)d_in[18];
    const float* W1         = (const float*)d_in[19];
    const float* b1         = (const float*)d_in[20];
    const float* W2         = (const float*)d_in[21];
    const float* b2         = (const float*)d_in[22];

    float* out   = (float*)d_out;
    float* prob  = out;
    float* h_new = out + B_EDGES;
    float* c_new = out + B_EDGES + (size_t)N_NODES * H;

    prep_weights_kernel<<<(KTILES * 32 * 32 * 4 + 255) / 256, 256>>>(Wx, Wh, b_gate);

    build_a_kernel<<<M_TILES, 256>>>(node_cont, ncat_codes, ncat_emb, h_prev);

    gemm_lstm_kernel<<<M_TILES * 4, 256>>>(c_prev, w_c, h_new, c_new);

    edge_mlp_kernel<<<B_EDGES / 16, 256>>>(
        src_ids, dst_ids, etype_ids, t_rel,
        ecat_codes, eid_emb, ecat_emb, time_W, time_b,
        W1, b1, W2, b2, h_new, prob);
}